// round 13
// baseline (speedup 1.0000x reference)
#include <cuda_runtime.h>
#include <cuda_fp16.h>
#include <cstdint>

// Problem constants
#define NA   50000
#define NB   200000
#define CA   256
#define CB   128
#define CX   384
#define CO   256
#define KT   8
#define MT   100000
#define KC   27
#define MC   120000
#define BN_EPS 1e-5f

// Device-resident buffers
__device__ float g_x[(size_t)NB * CO];                 // conv_t fp32 accumulator
__device__ __half g_xs[(size_t)NB * CX];               // x (BN+ReLU | feats_b) fp16
__device__ __half g_as[(size_t)NA * CA];               // feats_a fp16
__device__ __half g_Wt[(size_t)KT * CO * CA];          // W_t^T [z][n][k] fp16
__device__ __half g_Wc[(size_t)KC * CO * CX];          // W_c^T [z][n][k] fp16

// ===========================================================================
// PTX helpers (generic PTX only — tcgen05 unavailable at compute_103)
// ===========================================================================
__device__ __forceinline__ uint32_t smem_to_u32(const void* p) {
    uint32_t a;
    asm("{ .reg .u64 t; cvta.to.shared.u64 t, %1; cvt.u32.u64 %0, t; }" : "=r"(a) : "l"(p));
    return a;
}

#define CP_ASYNC_16(dst_u32, src_ptr) \
    asm volatile("cp.async.cg.shared.global [%0], [%1], 16;" \
                 :: "r"(dst_u32), "l"(src_ptr) : "memory")
#define CP_ASYNC_16Z(dst_u32, src_ptr, zf) \
    asm volatile("cp.async.cg.shared.global [%0], [%1], 16, %2;" \
                 :: "r"(dst_u32), "l"(src_ptr), "r"(zf) : "memory")
#define CP_ASYNC_COMMIT() asm volatile("cp.async.commit_group;" ::: "memory")
#define CP_ASYNC_WAIT3()  asm volatile("cp.async.wait_group 3;" ::: "memory")

#define LDSM_X4(r0, r1, r2, r3, addr) \
    asm volatile("ldmatrix.sync.aligned.m8n8.x4.shared.b16 {%0,%1,%2,%3}, [%4];" \
                 : "=r"(r0), "=r"(r1), "=r"(r2), "=r"(r3) : "r"(addr))

#define MMA_F16(d, a, b) \
    asm volatile("mma.sync.aligned.m16n8k16.row.col.f32.f16.f16.f32 " \
                 "{%0,%1,%2,%3}, {%4,%5,%6,%7}, {%8,%9}, {%0,%1,%2,%3};" \
                 : "+f"((d)[0]), "+f"((d)[1]), "+f"((d)[2]), "+f"((d)[3]) \
                 : "r"((a)[0]), "r"((a)[1]), "r"((a)[2]), "r"((a)[3]), \
                   "r"((b)[0]), "r"((b)[1]))

__device__ __forceinline__ void red_add_v4(float* p, float a, float b, float c, float d) {
    asm volatile("red.global.add.v4.f32 [%0], {%1, %2, %3, %4};"
                 :: "l"(p), "f"(a), "f"(b), "f"(c), "f"(d) : "memory");
}

// ===========================================================================
// Prep: transpose W [K][CIN][CO] -> [K][CO][CIN], fp16
// ===========================================================================
template <int CIN>
__global__ void prep_w_kernel(const float* __restrict__ W,
                              __half* __restrict__ wh) {
    __shared__ float t[32][33];
    const int z = blockIdx.z;
    const int k0 = blockIdx.y * 32, n0 = blockIdx.x * 32;
    const int tx = threadIdx.x, ty = threadIdx.y;   // (32, 8)
    #pragma unroll
    for (int i = 0; i < 4; ++i) {
        int k = k0 + ty + i * 8;
        t[ty + i * 8][tx] = W[((size_t)z * CIN + k) * CO + n0 + tx];
    }
    __syncthreads();
    #pragma unroll
    for (int i = 0; i < 4; ++i) {
        int n = n0 + ty + i * 8;
        wh[((size_t)z * CO + n) * CIN + k0 + tx] = __float2half_rn(t[tx][ty + i * 8]);
    }
}

// ===========================================================================
// Prep: feats_a -> fp16
// ===========================================================================
__global__ void prep_a_kernel(const float* __restrict__ feats_a) {
    int row = blockIdx.x;
    int t = threadIdx.x;          // 64 threads, 4 floats each
    float4 v = reinterpret_cast<const float4*>(feats_a + (size_t)row * CA)[t];
    __half2 h0 = __floats2half2_rn(v.x, v.y);
    __half2 h1 = __floats2half2_rn(v.z, v.w);
    *reinterpret_cast<__half2*>(g_as + (size_t)row * CA + 4 * t)     = h0;
    *reinterpret_cast<__half2*>(g_as + (size_t)row * CA + 4 * t + 2) = h1;
}

// ===========================================================================
// BN+ReLU on conv_t accumulator + concat feats_b -> fp16 g_xs
// ===========================================================================
__global__ void bn_split_x_kernel(const float* __restrict__ feats_b,
                                  const float* __restrict__ gamma,
                                  const float* __restrict__ beta,
                                  const float* __restrict__ mean,
                                  const float* __restrict__ var) {
    int row = blockIdx.x;
    int t = threadIdx.x;          // 96 active
    if (t >= CX / 4) return;
    float4 v;
    if (t < CA / 4) {
        v = reinterpret_cast<const float4*>(g_x + (size_t)row * CO)[t];
        float4 gm = reinterpret_cast<const float4*>(gamma)[t];
        float4 bt = reinterpret_cast<const float4*>(beta)[t];
        float4 mn = reinterpret_cast<const float4*>(mean)[t];
        float4 vr = reinterpret_cast<const float4*>(var)[t];
        v.x = fmaxf(fmaf(v.x - mn.x, gm.x * rsqrtf(vr.x + BN_EPS), bt.x), 0.f);
        v.y = fmaxf(fmaf(v.y - mn.y, gm.y * rsqrtf(vr.y + BN_EPS), bt.y), 0.f);
        v.z = fmaxf(fmaf(v.z - mn.z, gm.z * rsqrtf(vr.z + BN_EPS), bt.z), 0.f);
        v.w = fmaxf(fmaf(v.w - mn.w, gm.w * rsqrtf(vr.w + BN_EPS), bt.w), 0.f);
    } else {
        v = reinterpret_cast<const float4*>(feats_b + (size_t)row * CB)[t - CA / 4];
    }
    __half2 h0 = __floats2half2_rn(v.x, v.y);
    __half2 h1 = __floats2half2_rn(v.z, v.w);
    __half* xs = g_xs + (size_t)row * CX + 4 * t;
    *reinterpret_cast<__half2*>(xs)     = h0;
    *reinterpret_cast<__half2*>(xs + 2) = h1;
}

// zero both fp32 accumulators in one kernel
__global__ void zero2_kernel(float* __restrict__ p0, float* __restrict__ p1, int n4) {
    int i = blockIdx.x * blockDim.x + threadIdx.x;
    if (i < n4) {
        reinterpret_cast<float4*>(p0)[i] = make_float4(0.f, 0.f, 0.f, 0.f);
        reinterpret_cast<float4*>(p1)[i] = make_float4(0.f, 0.f, 0.f, 0.f);
    }
}

// ===========================================================================
// PERSISTENT sparse conv: each CTA walks tiles (z-major), 5-stage cp.async
// pipeline runs continuously ACROSS tile boundaries; epilogue uses a
// dedicated staging region (syncwarp only) overlapped with next tile's loads.
// CTA tile: 128 pairs x 256 out-ch. 512 threads, 16 warps (4M x 4N).
// Stage: A 10240 | B 20480 = 30720 B x 5 + staging 69632 = 223232 B.
// ===========================================================================
#define OFF_B     10240
#define BUF_SZ    30720
#define NSTAGES   5
#define STG_OFF   (NSTAGES * BUF_SZ)
#define SMEM_TOTAL (STG_OFF + 16 * 16 * 68 * 4)

template <int CIN, bool DST_GX>
__global__ void __launch_bounds__(512, 1)
spconv_mma_kernel(const __half* __restrict__ xs,
                  const __half* __restrict__ Wh,
                  const int* __restrict__ in_map,
                  const int* __restrict__ out_map,
                  float* __restrict__ out_param,
                  int M, int nmb, int ntiles) {
    extern __shared__ char smc[];
    const uint32_t sb = smem_to_u32(smc);
    float* outb = DST_GX ? (float*)g_x : out_param;

    const int tid  = threadIdx.x;
    const int lane = tid & 31;
    const int w    = tid >> 5;       // 0..15
    const int wm   = w & 3;          // 4 M-groups of 32 rows
    const int wn   = w >> 2;         // 4 N-groups of 64 cols

    constexpr int NC = CIN / 32;

    // per-thread load assignments
    const int ar = tid >> 2;         // A row 0..127
    const int as = tid & 3;          // 16B quarter
    const int br = tid >> 1;         // B n-row 0..255
    const int bs = tid & 1;          // 32B half

    // ldmatrix lane addressing (bytes within a stage)
    const uint32_t aoff = (uint32_t)(((wm * 32 + (lane & 15)) * 40 + ((lane >> 4) * 8)) * 2);
    const uint32_t boff = (uint32_t)(((wn * 64 + (lane & 7) + ((lane >> 4) * 8)) * 40
                                      + (((lane >> 3) & 1) * 8)) * 2);
    const uint32_t dstA = sb + (uint32_t)(ar * 80 + as * 16);
    const uint32_t dstB = sb + OFF_B + (uint32_t)(br * 80 + bs * 32);

    const int nt_mine = (ntiles - (int)blockIdx.x + (int)gridDim.x - 1) / (int)gridDim.x;
    if (nt_mine <= 0) return;
    const int TC = nt_mine * NC;

    // ---- loader state (advances tile-by-tile ahead of compute)
    int l_s = -1;                    // loader's tile seq index
    const char* rowp_l = (const char*)xs;
    uint32_t zf_l = 0;
    const __half* hb_l = Wh;
    int st_l = 0;                    // loader stage (mod NSTAGES)

    auto load_chunk = [&](int cc) {
        const int s = cc / NC, c = cc - s * NC;
        if (s != l_s) {
            l_s = s;
            const int tile = (int)blockIdx.x + s * (int)gridDim.x;
            const int zz = tile / nmb, mb = tile - zz * nmb;
            const int mrow = mb * 128 + ar;
            zf_l = 0; rowp_l = (const char*)xs;
            if (mrow < M) {
                rowp_l = (const char*)(xs + (size_t)in_map[(size_t)zz * M + mrow] * CIN);
                zf_l = 16;
            }
            hb_l = Wh + ((size_t)zz * CO + br) * CIN + bs * 16;
        }
        const uint32_t bo = (uint32_t)(st_l * BUF_SZ);
        st_l = (st_l + 1 == NSTAGES) ? 0 : st_l + 1;
        CP_ASYNC_16Z(dstA + bo, rowp_l + c * 64 + as * 16, zf_l);
        const __half* hk = hb_l + c * 32;
        CP_ASYNC_16(dstB + bo,      hk);
        CP_ASYNC_16(dstB + bo + 16, hk + 8);
    };

    // ---- prologue: 4 chunks in flight
    int cc = 0;
    #pragma unroll
    for (int p = 0; p < 4; ++p) {
        if (cc < TC) load_chunk(cc);
        CP_ASYNC_COMMIT();
        ++cc;
    }

    int st_c = 0;                    // compute stage
    float* ws = reinterpret_cast<float*>(smc + STG_OFF) + w * (16 * 68);

    for (int s = 0; s < nt_mine; ++s) {
        const int tile = (int)blockIdx.x + s * (int)gridDim.x;
        const int zz = tile / nmb, mb = tile - zz * nmb;
        const int m0 = mb * 128;
        const size_t zM = (size_t)zz * M;

        float acc[2][8][4];
        #pragma unroll
        for (int i = 0; i < 2; ++i)
            #pragma unroll
            for (int j = 0; j < 8; ++j)
                #pragma unroll
                for (int q = 0; q < 4; ++q) acc[i][j][q] = 0.f;

        for (int c = 0; c < NC; ++c) {
            CP_ASYNC_WAIT3();
            __syncthreads();
            if (cc < TC) load_chunk(cc);
            CP_ASYNC_COMMIT();
            ++cc;

            const uint32_t bo = (uint32_t)(st_c * BUF_SZ);
            st_c = (st_c + 1 == NSTAGES) ? 0 : st_c + 1;
            #pragma unroll
            for (int ks = 0; ks < 2; ++ks) {
                const uint32_t ka = (uint32_t)(ks * 32);
                uint32_t ah[2][4];
                #pragma unroll
                for (int i = 0; i < 2; ++i) {
                    uint32_t pa = sb + bo + aoff + ka + (uint32_t)(i * 1280);
                    LDSM_X4(ah[i][0], ah[i][1], ah[i][2], ah[i][3], pa);
                }
                #pragma unroll
                for (int g = 0; g < 4; ++g) {
                    uint32_t bh[4];
                    uint32_t pb = sb + bo + OFF_B + boff + ka + (uint32_t)(g * 1280);
                    LDSM_X4(bh[0], bh[1], bh[2], bh[3], pb);
                    #pragma unroll
                    for (int i = 0; i < 2; ++i) {
                        MMA_F16(acc[i][2 * g],     ah[i], bh);
                        MMA_F16(acc[i][2 * g + 1], ah[i], bh + 2);
                    }
                }
            }
        }

        // ---- epilogue (warp-private staging; overlaps next tile's loads)
        const int ncol = wn * 64 + (lane & 15) * 4;
        #pragma unroll
        for (int i = 0; i < 2; ++i) {
            #pragma unroll
            for (int j = 0; j < 8; ++j) {
                int colo = j * 8 + 2 * (lane & 3);
                *reinterpret_cast<float2*>(ws + (lane >> 2) * 68 + colo) =
                    make_float2(acc[i][j][0], acc[i][j][1]);
                *reinterpret_cast<float2*>(ws + ((lane >> 2) + 8) * 68 + colo) =
                    make_float2(acc[i][j][2], acc[i][j][3]);
            }
            __syncwarp();
            #pragma unroll
            for (int r = 0; r < 8; ++r) {
                int row = r * 2 + (lane >> 4);
                int mrow = m0 + wm * 32 + i * 16 + row;
                if (mrow < M) {
                    int o = out_map[zM + mrow];
                    float4 v = *reinterpret_cast<float4*>(ws + row * 68 + (lane & 15) * 4);
                    red_add_v4(outb + (size_t)o * CO + ncol, v.x, v.y, v.z, v.w);
                }
            }
            __syncwarp();
        }
    }
}

// ===========================================================================
// BN (eval) + ReLU on output
// ===========================================================================
__global__ void bn_relu_kernel(float* __restrict__ buf,
                               const float* __restrict__ gamma,
                               const float* __restrict__ beta,
                               const float* __restrict__ mean,
                               const float* __restrict__ var) {
    int c = threadIdx.x;
    float s  = gamma[c] * rsqrtf(var[c] + BN_EPS);
    float sh = beta[c] - mean[c] * s;
    for (int row = blockIdx.x; row < NB; row += gridDim.x) {
        size_t idx = (size_t)row * CO + c;
        buf[idx] = fmaxf(fmaf(buf[idx], s, sh), 0.f);
    }
}

// ===========================================================================
extern "C" void kernel_launch(void* const* d_in, const int* in_sizes, int n_in,
                              void* d_out, int out_size) {
    const float* feats_a    = (const float*)d_in[0];
    const float* feats_b    = (const float*)d_in[1];
    const float* W_t        = (const float*)d_in[2];
    const float* bn_t_gamma = (const float*)d_in[3];
    const float* bn_t_beta  = (const float*)d_in[4];
    const float* bn_t_mean  = (const float*)d_in[5];
    const float* bn_t_var   = (const float*)d_in[6];
    const float* W_c        = (const float*)d_in[7];
    const float* bn_c_gamma = (const float*)d_in[8];
    const float* bn_c_beta  = (const float*)d_in[9];
    const float* bn_c_mean  = (const float*)d_in[10];
    const float* bn_c_var   = (const float*)d_in[11];
    const int*   in_map_t   = (const int*)d_in[12];
    const int*   out_map_t  = (const int*)d_in[13];
    const int*   in_map_c   = (const int*)d_in[14];
    const int*   out_map_c  = (const int*)d_in[15];
    float* out = (float*)d_out;

    int nsm = 148;
    cudaDeviceGetAttribute(&nsm, cudaDevAttrMultiProcessorCount, 0);

    cudaFuncSetAttribute(spconv_mma_kernel<CA, true>,
                         cudaFuncAttributeMaxDynamicSharedMemorySize, SMEM_TOTAL);
    cudaFuncSetAttribute(spconv_mma_kernel<CX, false>,
                         cudaFuncAttributeMaxDynamicSharedMemorySize, SMEM_TOTAL);

    void *wt, *wc, *gx, *gas, *gxs;
    cudaGetSymbolAddress(&wt, g_Wt);
    cudaGetSymbolAddress(&wc, g_Wc);
    cudaGetSymbolAddress(&gx, g_x);
    cudaGetSymbolAddress(&gas, g_as);
    cudaGetSymbolAddress(&gxs, g_xs);

    // 0) weight transpose + fp16 ; feats_a fp16 ; zero accumulators
    prep_w_kernel<CA><<<dim3(CO / 32, CA / 32, KT), dim3(32, 8)>>>(W_t, (__half*)wt);
    prep_w_kernel<CX><<<dim3(CO / 32, CX / 32, KC), dim3(32, 8)>>>(W_c, (__half*)wc);
    prep_a_kernel<<<NA, 64>>>(feats_a);
    {
        int n4 = (int)((size_t)NB * CO / 4);
        zero2_kernel<<<(n4 + 255) / 256, 256>>>((float*)gx, out, n4);
    }

    // 1) transpose conv: g_as -> g_x (fp32 accum) — persistent
    {
        int nmb = (MT + 127) / 128;
        int ntiles = nmb * KT;
        spconv_mma_kernel<CA, true><<<nsm, 512, SMEM_TOTAL>>>(
            (const __half*)gas, (const __half*)wt, in_map_t, out_map_t,
            nullptr, MT, nmb, ntiles);
    }

    // 2) BN+ReLU + concat -> g_xs (fp16)
    bn_split_x_kernel<<<NB, 128>>>(feats_b, bn_t_gamma, bn_t_beta,
                                   bn_t_mean, bn_t_var);

    // 3) 3x3x3 conv: g_xs -> out — persistent
    {
        int nmb = (MC + 127) / 128;
        int ntiles = nmb * KC;
        spconv_mma_kernel<CX, false><<<nsm, 512, SMEM_TOTAL>>>(
            (const __half*)gxs, (const __half*)wc, in_map_c, out_map_c,
            out, MC, nmb, ntiles);
    }

    // 4) BN + ReLU on output
    bn_relu_kernel<<<4096, 256>>>(out, bn_c_gamma, bn_c_beta,
                                  bn_c_mean, bn_c_var);
}

// round 14
// speedup vs baseline: 1.1216x; 1.1216x over previous
#include <cuda_runtime.h>
#include <cuda_fp16.h>
#include <cstdint>

// Problem constants
#define NA   50000
#define NB   200000
#define CA   256
#define CB   128
#define CX   384
#define CO   256
#define KT   8
#define MT   100000
#define KC   27
#define MC   120000
#define BN_EPS 1e-5f

// Device-resident buffers
__device__ float g_x[(size_t)NB * CO];                 // conv_t fp32 accumulator
__device__ __half g_xs[(size_t)NB * CX];               // x (BN+ReLU | feats_b) fp16
__device__ __half g_as[(size_t)NA * CA];               // feats_a fp16
__device__ __half g_Wt[(size_t)KT * CO * CA];          // W_t^T [z][n][k] fp16
__device__ __half g_Wc[(size_t)KC * CO * CX];          // W_c^T [z][n][k] fp16

// ===========================================================================
// PTX helpers (generic PTX only — tcgen05 unavailable at compute_103)
// ===========================================================================
__device__ __forceinline__ uint32_t smem_to_u32(const void* p) {
    uint32_t a;
    asm("{ .reg .u64 t; cvta.to.shared.u64 t, %1; cvt.u32.u64 %0, t; }" : "=r"(a) : "l"(p));
    return a;
}

#define CP_ASYNC_16(dst_u32, src_ptr) \
    asm volatile("cp.async.cg.shared.global [%0], [%1], 16;" \
                 :: "r"(dst_u32), "l"(src_ptr) : "memory")
#define CP_ASYNC_16Z(dst_u32, src_ptr, zf) \
    asm volatile("cp.async.cg.shared.global [%0], [%1], 16, %2;" \
                 :: "r"(dst_u32), "l"(src_ptr), "r"(zf) : "memory")
#define CP_ASYNC_COMMIT() asm volatile("cp.async.commit_group;" ::: "memory")
#define CP_ASYNC_WAIT3()  asm volatile("cp.async.wait_group 3;" ::: "memory")

#define LDSM_X4(r0, r1, r2, r3, addr) \
    asm volatile("ldmatrix.sync.aligned.m8n8.x4.shared.b16 {%0,%1,%2,%3}, [%4];" \
                 : "=r"(r0), "=r"(r1), "=r"(r2), "=r"(r3) : "r"(addr))

#define MMA_F16(d, a, b) \
    asm volatile("mma.sync.aligned.m16n8k16.row.col.f32.f16.f16.f32 " \
                 "{%0,%1,%2,%3}, {%4,%5,%6,%7}, {%8,%9}, {%0,%1,%2,%3};" \
                 : "+f"((d)[0]), "+f"((d)[1]), "+f"((d)[2]), "+f"((d)[3]) \
                 : "r"((a)[0]), "r"((a)[1]), "r"((a)[2]), "r"((a)[3]), \
                   "r"((b)[0]), "r"((b)[1]))

__device__ __forceinline__ void red_add_v4(float* p, float a, float b, float c, float d) {
    asm volatile("red.global.add.v4.f32 [%0], {%1, %2, %3, %4};"
                 :: "l"(p), "f"(a), "f"(b), "f"(c), "f"(d) : "memory");
}

// ===========================================================================
// Prep: transpose W [K][CIN][CO] -> [K][CO][CIN], fp16
// ===========================================================================
template <int CIN>
__global__ void prep_w_kernel(const float* __restrict__ W,
                              __half* __restrict__ wh) {
    __shared__ float t[32][33];
    const int z = blockIdx.z;
    const int k0 = blockIdx.y * 32, n0 = blockIdx.x * 32;
    const int tx = threadIdx.x, ty = threadIdx.y;   // (32, 8)
    #pragma unroll
    for (int i = 0; i < 4; ++i) {
        int k = k0 + ty + i * 8;
        t[ty + i * 8][tx] = W[((size_t)z * CIN + k) * CO + n0 + tx];
    }
    __syncthreads();
    #pragma unroll
    for (int i = 0; i < 4; ++i) {
        int n = n0 + ty + i * 8;
        wh[((size_t)z * CO + n) * CIN + k0 + tx] = __float2half_rn(t[tx][ty + i * 8]);
    }
}

// ===========================================================================
// Prep: feats_a -> fp16
// ===========================================================================
__global__ void prep_a_kernel(const float* __restrict__ feats_a) {
    int row = blockIdx.x;
    int t = threadIdx.x;          // 64 threads, 4 floats each
    float4 v = reinterpret_cast<const float4*>(feats_a + (size_t)row * CA)[t];
    __half2 h0 = __floats2half2_rn(v.x, v.y);
    __half2 h1 = __floats2half2_rn(v.z, v.w);
    *reinterpret_cast<__half2*>(g_as + (size_t)row * CA + 4 * t)     = h0;
    *reinterpret_cast<__half2*>(g_as + (size_t)row * CA + 4 * t + 2) = h1;
}

// ===========================================================================
// BN+ReLU on conv_t accumulator + concat feats_b -> fp16 g_xs
// ===========================================================================
__global__ void bn_split_x_kernel(const float* __restrict__ feats_b,
                                  const float* __restrict__ gamma,
                                  const float* __restrict__ beta,
                                  const float* __restrict__ mean,
                                  const float* __restrict__ var) {
    int row = blockIdx.x;
    int t = threadIdx.x;          // 96 active
    if (t >= CX / 4) return;
    float4 v;
    if (t < CA / 4) {
        v = reinterpret_cast<const float4*>(g_x + (size_t)row * CO)[t];
        float4 gm = reinterpret_cast<const float4*>(gamma)[t];
        float4 bt = reinterpret_cast<const float4*>(beta)[t];
        float4 mn = reinterpret_cast<const float4*>(mean)[t];
        float4 vr = reinterpret_cast<const float4*>(var)[t];
        v.x = fmaxf(fmaf(v.x - mn.x, gm.x * rsqrtf(vr.x + BN_EPS), bt.x), 0.f);
        v.y = fmaxf(fmaf(v.y - mn.y, gm.y * rsqrtf(vr.y + BN_EPS), bt.y), 0.f);
        v.z = fmaxf(fmaf(v.z - mn.z, gm.z * rsqrtf(vr.z + BN_EPS), bt.z), 0.f);
        v.w = fmaxf(fmaf(v.w - mn.w, gm.w * rsqrtf(vr.w + BN_EPS), bt.w), 0.f);
    } else {
        v = reinterpret_cast<const float4*>(feats_b + (size_t)row * CB)[t - CA / 4];
    }
    __half2 h0 = __floats2half2_rn(v.x, v.y);
    __half2 h1 = __floats2half2_rn(v.z, v.w);
    __half* xs = g_xs + (size_t)row * CX + 4 * t;
    *reinterpret_cast<__half2*>(xs)     = h0;
    *reinterpret_cast<__half2*>(xs + 2) = h1;
}

// zero both fp32 accumulators in one kernel
__global__ void zero2_kernel(float* __restrict__ p0, float* __restrict__ p1, int n4) {
    int i = blockIdx.x * blockDim.x + threadIdx.x;
    if (i < n4) {
        reinterpret_cast<float4*>(p0)[i] = make_float4(0.f, 0.f, 0.f, 0.f);
        reinterpret_cast<float4*>(p1)[i] = make_float4(0.f, 0.f, 0.f, 0.f);
    }
}

// ===========================================================================
// Sparse conv (single fp16 pass): A fp16 x W fp16 -> fp32 acc -> red.v4
// CTA tile: 128 pairs x 256 out-ch. 512 threads, 16 warps (4M x 4N),
// warp tile 32x64. K chunks of 32, 5-stage cp.async pipeline (wait_group 3).
// Epilogue uses a DEDICATED staging region -> no pre-epilogue syncthreads;
// warps drain their atomic bursts independently.
// Stage: A 10240 | B 20480 = 30720 B x 5 = 153600 + staging 69632 = 223232 B.
// ===========================================================================
#define OFF_B     10240
#define BUF_SZ    30720
#define NSTAGES   5
#define STG_OFF   (NSTAGES * BUF_SZ)
#define SMEM_TOTAL (STG_OFF + 16 * 16 * 68 * 4)

template <int CIN, bool DST_GX>
__global__ void __launch_bounds__(512, 1)
spconv_mma_kernel(const __half* __restrict__ xs,
                  const __half* __restrict__ Wh,
                  const int* __restrict__ in_map,
                  const int* __restrict__ out_map,
                  float* __restrict__ out_param,
                  int M) {
    extern __shared__ char smc[];
    const uint32_t sb = smem_to_u32(smc);
    float* outb = DST_GX ? (float*)g_x : out_param;

    const int tid  = threadIdx.x;
    const int lane = tid & 31;
    const int w    = tid >> 5;       // 0..15
    const int wm   = w & 3;          // 4 M-groups of 32 rows
    const int wn   = w >> 2;         // 4 N-groups of 64 cols

    const int z  = blockIdx.z;
    const int m0 = blockIdx.x * 128;
    const size_t zM = (size_t)z * M;

    // ---- A gather: thread -> (row = tid>>2, 16B quarter = tid&3)
    const int ar = tid >> 2;         // 0..127
    const int as = tid & 3;
    const char* rowp = (const char*)xs;
    uint32_t zf = 0;
    if (m0 + ar < M) {
        rowp = (const char*)(xs + (size_t)in_map[zM + m0 + ar] * CIN);
        zf = 16;
    }
    const uint32_t dstA = sb + (uint32_t)(ar * 80 + as * 16);

    // ---- B: thread -> (n-row = tid>>1, 32B half = tid&1)
    const int br = tid >> 1;         // 0..255
    const int bs = tid & 1;
    const __half* hb = Wh + ((size_t)z * CO + br) * CIN + bs * 16;
    const uint32_t dstB = sb + OFF_B + (uint32_t)(br * 80 + bs * 32);

    // ---- ldmatrix lane addressing (bytes within a stage)
    const uint32_t aoff = (uint32_t)(((wm * 32 + (lane & 15)) * 40 + ((lane >> 4) * 8)) * 2);
    const uint32_t boff = (uint32_t)(((wn * 64 + (lane & 7) + ((lane >> 4) * 8)) * 40
                                      + (((lane >> 3) & 1) * 8)) * 2);

    float acc[2][8][4];
    #pragma unroll
    for (int i = 0; i < 2; ++i)
        #pragma unroll
        for (int j = 0; j < 8; ++j)
            #pragma unroll
            for (int q = 0; q < 4; ++q) acc[i][j][q] = 0.f;

    constexpr int NC = CIN / 32;

    auto load_chunk = [&](int c) {
        const uint32_t bo = (uint32_t)((c % NSTAGES) * BUF_SZ);
        CP_ASYNC_16Z(dstA + bo, rowp + c * 64 + as * 16, zf);
        const __half* hk = hb + c * 32;
        CP_ASYNC_16(dstB + bo,      hk);
        CP_ASYNC_16(dstB + bo + 16, hk + 8);
    };

    load_chunk(0); CP_ASYNC_COMMIT();
    load_chunk(1); CP_ASYNC_COMMIT();
    load_chunk(2); CP_ASYNC_COMMIT();
    load_chunk(3); CP_ASYNC_COMMIT();

    for (int c = 0; c < NC; ++c) {
        CP_ASYNC_WAIT3();
        __syncthreads();
        if (c + 4 < NC) load_chunk(c + 4);
        CP_ASYNC_COMMIT();

        const uint32_t bo = (uint32_t)((c % NSTAGES) * BUF_SZ);
        #pragma unroll
        for (int ks = 0; ks < 2; ++ks) {
            const uint32_t ka = (uint32_t)(ks * 32);
            uint32_t ah[2][4];
            #pragma unroll
            for (int i = 0; i < 2; ++i) {
                uint32_t pa = sb + bo + aoff + ka + (uint32_t)(i * 1280);
                LDSM_X4(ah[i][0], ah[i][1], ah[i][2], ah[i][3], pa);
            }
            #pragma unroll
            for (int g = 0; g < 4; ++g) {
                uint32_t bh[4];
                uint32_t pb = sb + bo + OFF_B + boff + ka + (uint32_t)(g * 1280);
                LDSM_X4(bh[0], bh[1], bh[2], bh[3], pb);
                #pragma unroll
                for (int i = 0; i < 2; ++i) {
                    MMA_F16(acc[i][2 * g],     ah[i], bh);
                    MMA_F16(acc[i][2 * g + 1], ah[i], bh + 2);
                }
            }
        }
    }

    // ---- epilogue: warp-private staging (dedicated region, no syncthreads)
    float* ws = reinterpret_cast<float*>(smc + STG_OFF) + w * (16 * 68);
    const int ncol = wn * 64 + (lane & 15) * 4;
    #pragma unroll
    for (int i = 0; i < 2; ++i) {
        #pragma unroll
        for (int j = 0; j < 8; ++j) {
            int colo = j * 8 + 2 * (lane & 3);
            *reinterpret_cast<float2*>(ws + (lane >> 2) * 68 + colo) =
                make_float2(acc[i][j][0], acc[i][j][1]);
            *reinterpret_cast<float2*>(ws + ((lane >> 2) + 8) * 68 + colo) =
                make_float2(acc[i][j][2], acc[i][j][3]);
        }
        __syncwarp();
        #pragma unroll
        for (int r = 0; r < 8; ++r) {
            int row = r * 2 + (lane >> 4);
            int mrow = m0 + wm * 32 + i * 16 + row;
            if (mrow < M) {
                int o = out_map[zM + mrow];
                float4 v = *reinterpret_cast<float4*>(ws + row * 68 + (lane & 15) * 4);
                red_add_v4(outb + (size_t)o * CO + ncol, v.x, v.y, v.z, v.w);
            }
        }
        __syncwarp();
    }
}

// ===========================================================================
// BN (eval) + ReLU on output
// ===========================================================================
__global__ void bn_relu_kernel(float* __restrict__ buf,
                               const float* __restrict__ gamma,
                               const float* __restrict__ beta,
                               const float* __restrict__ mean,
                               const float* __restrict__ var) {
    int c = threadIdx.x;
    float s  = gamma[c] * rsqrtf(var[c] + BN_EPS);
    float sh = beta[c] - mean[c] * s;
    for (int row = blockIdx.x; row < NB; row += gridDim.x) {
        size_t idx = (size_t)row * CO + c;
        buf[idx] = fmaxf(fmaf(buf[idx], s, sh), 0.f);
    }
}

// ===========================================================================
extern "C" void kernel_launch(void* const* d_in, const int* in_sizes, int n_in,
                              void* d_out, int out_size) {
    const float* feats_a    = (const float*)d_in[0];
    const float* feats_b    = (const float*)d_in[1];
    const float* W_t        = (const float*)d_in[2];
    const float* bn_t_gamma = (const float*)d_in[3];
    const float* bn_t_beta  = (const float*)d_in[4];
    const float* bn_t_mean  = (const float*)d_in[5];
    const float* bn_t_var   = (const float*)d_in[6];
    const float* W_c        = (const float*)d_in[7];
    const float* bn_c_gamma = (const float*)d_in[8];
    const float* bn_c_beta  = (const float*)d_in[9];
    const float* bn_c_mean  = (const float*)d_in[10];
    const float* bn_c_var   = (const float*)d_in[11];
    const int*   in_map_t   = (const int*)d_in[12];
    const int*   out_map_t  = (const int*)d_in[13];
    const int*   in_map_c   = (const int*)d_in[14];
    const int*   out_map_c  = (const int*)d_in[15];
    float* out = (float*)d_out;

    cudaFuncSetAttribute(spconv_mma_kernel<CA, true>,
                         cudaFuncAttributeMaxDynamicSharedMemorySize, SMEM_TOTAL);
    cudaFuncSetAttribute(spconv_mma_kernel<CX, false>,
                         cudaFuncAttributeMaxDynamicSharedMemorySize, SMEM_TOTAL);

    void *wt, *wc, *gx, *gas, *gxs;
    cudaGetSymbolAddress(&wt, g_Wt);
    cudaGetSymbolAddress(&wc, g_Wc);
    cudaGetSymbolAddress(&gx, g_x);
    cudaGetSymbolAddress(&gas, g_as);
    cudaGetSymbolAddress(&gxs, g_xs);

    // 0) weight transpose + fp16 ; feats_a fp16 ; zero accumulators
    prep_w_kernel<CA><<<dim3(CO / 32, CA / 32, KT), dim3(32, 8)>>>(W_t, (__half*)wt);
    prep_w_kernel<CX><<<dim3(CO / 32, CX / 32, KC), dim3(32, 8)>>>(W_c, (__half*)wc);
    prep_a_kernel<<<NA, 64>>>(feats_a);
    {
        int n4 = (int)((size_t)NB * CO / 4);
        zero2_kernel<<<(n4 + 255) / 256, 256>>>((float*)gx, out, n4);
    }

    // 1) transpose conv: g_as -> g_x (fp32 accum)
    {
        dim3 grid((MT + 127) / 128, 1, KT);
        spconv_mma_kernel<CA, true><<<grid, 512, SMEM_TOTAL>>>(
            (const __half*)gas, (const __half*)wt, in_map_t, out_map_t, nullptr, MT);
    }

    // 2) BN+ReLU + concat -> g_xs (fp16)
    bn_split_x_kernel<<<NB, 128>>>(feats_b, bn_t_gamma, bn_t_beta,
                                   bn_t_mean, bn_t_var);

    // 3) 3x3x3 conv: g_xs -> out
    {
        dim3 grid((MC + 127) / 128, 1, KC);
        spconv_mma_kernel<CX, false><<<grid, 512, SMEM_TOTAL>>>(
            (const __half*)gxs, (const __half*)wc, in_map_c, out_map_c, out, MC);
    }

    // 4) BN + ReLU on output
    bn_relu_kernel<<<4096, 256>>>(out, bn_c_gamma, bn_c_beta,
                                  bn_c_mean, bn_c_var);
}

// round 17
// speedup vs baseline: 1.5454x; 1.3778x over previous
#include <cuda_runtime.h>
#include <cuda_fp16.h>
#include <cstdint>

// Problem constants
#define NA   50000
#define NB   200000
#define CA   256
#define CB   128
#define CX   384
#define CO   256
#define KT   8
#define MT   100000
#define KC   27
#define MC   120000
#define BN_EPS 1e-5f

// Device-resident buffers
__device__ float g_x[(size_t)NB * CO];                 // conv_t fp32 accumulator
__device__ __half g_xs[(size_t)NB * CX];               // x (BN+ReLU | feats_b) fp16
__device__ __half g_as[(size_t)NA * CA];               // feats_a fp16
__device__ __half g_Wt[(size_t)KT * CO * CA];          // W_t^T [z][n][k] fp16
__device__ __half g_Wc[(size_t)KC * CO * CX];          // W_c^T [z][n][k] fp16

// ===========================================================================
// PTX helpers (generic PTX only — tcgen05 unavailable at compute_103)
// ===========================================================================
__device__ __forceinline__ uint32_t smem_to_u32(const void* p) {
    uint32_t a;
    asm("{ .reg .u64 t; cvta.to.shared.u64 t, %1; cvt.u32.u64 %0, t; }" : "=r"(a) : "l"(p));
    return a;
}

#define CP_ASYNC_16(dst_u32, src_ptr) \
    asm volatile("cp.async.cg.shared.global [%0], [%1], 16;" \
                 :: "r"(dst_u32), "l"(src_ptr) : "memory")
#define CP_ASYNC_16Z(dst_u32, src_ptr, zf) \
    asm volatile("cp.async.cg.shared.global [%0], [%1], 16, %2;" \
                 :: "r"(dst_u32), "l"(src_ptr), "r"(zf) : "memory")
#define CP_ASYNC_COMMIT() asm volatile("cp.async.commit_group;" ::: "memory")
#define CP_ASYNC_WAIT2()  asm volatile("cp.async.wait_group 2;" ::: "memory")

#define LDSM_X4(r0, r1, r2, r3, addr) \
    asm volatile("ldmatrix.sync.aligned.m8n8.x4.shared.b16 {%0,%1,%2,%3}, [%4];" \
                 : "=r"(r0), "=r"(r1), "=r"(r2), "=r"(r3) : "r"(addr))

#define MMA_F16(d, a, b) \
    asm volatile("mma.sync.aligned.m16n8k16.row.col.f32.f16.f16.f32 " \
                 "{%0,%1,%2,%3}, {%4,%5,%6,%7}, {%8,%9}, {%0,%1,%2,%3};" \
                 : "+f"((d)[0]), "+f"((d)[1]), "+f"((d)[2]), "+f"((d)[3]) \
                 : "r"((a)[0]), "r"((a)[1]), "r"((a)[2]), "r"((a)[3]), \
                   "r"((b)[0]), "r"((b)[1]))

__device__ __forceinline__ void red_add_v4(float* p, float a, float b, float c, float d) {
    asm volatile("red.global.add.v4.f32 [%0], {%1, %2, %3, %4};"
                 :: "l"(p), "f"(a), "f"(b), "f"(c), "f"(d) : "memory");
}

// ===========================================================================
// Prep: transpose W [K][CIN][CO] -> [K][CO][CIN], fp16
// ===========================================================================
template <int CIN>
__global__ void prep_w_kernel(const float* __restrict__ W,
                              __half* __restrict__ wh) {
    __shared__ float t[32][33];
    const int z = blockIdx.z;
    const int k0 = blockIdx.y * 32, n0 = blockIdx.x * 32;
    const int tx = threadIdx.x, ty = threadIdx.y;   // (32, 8)
    #pragma unroll
    for (int i = 0; i < 4; ++i) {
        int k = k0 + ty + i * 8;
        t[ty + i * 8][tx] = W[((size_t)z * CIN + k) * CO + n0 + tx];
    }
    __syncthreads();
    #pragma unroll
    for (int i = 0; i < 4; ++i) {
        int n = n0 + ty + i * 8;
        wh[((size_t)z * CO + n) * CIN + k0 + tx] = __float2half_rn(t[tx][ty + i * 8]);
    }
}

// ===========================================================================
// Prep: feats_a -> fp16
// ===========================================================================
__global__ void prep_a_kernel(const float* __restrict__ feats_a) {
    int row = blockIdx.x;
    int t = threadIdx.x;          // 64 threads, 4 floats each
    float4 v = reinterpret_cast<const float4*>(feats_a + (size_t)row * CA)[t];
    __half2 h0 = __floats2half2_rn(v.x, v.y);
    __half2 h1 = __floats2half2_rn(v.z, v.w);
    *reinterpret_cast<__half2*>(g_as + (size_t)row * CA + 4 * t)     = h0;
    *reinterpret_cast<__half2*>(g_as + (size_t)row * CA + 4 * t + 2) = h1;
}

// ===========================================================================
// BN+ReLU on conv_t accumulator + concat feats_b -> fp16 g_xs
// 96 threads/block, all active (t < CX/4 = 96 by construction)
// ===========================================================================
__global__ void bn_split_x_kernel(const float* __restrict__ feats_b,
                                  const float* __restrict__ gamma,
                                  const float* __restrict__ beta,
                                  const float* __restrict__ mean,
                                  const float* __restrict__ var) {
    int row = blockIdx.x;
    int t = threadIdx.x;          // 0..95, all active
    float4 v;
    if (t < CA / 4) {
        v = reinterpret_cast<const float4*>(g_x + (size_t)row * CO)[t];
        float4 gm = reinterpret_cast<const float4*>(gamma)[t];
        float4 bt = reinterpret_cast<const float4*>(beta)[t];
        float4 mn = reinterpret_cast<const float4*>(mean)[t];
        float4 vr = reinterpret_cast<const float4*>(var)[t];
        v.x = fmaxf(fmaf(v.x - mn.x, gm.x * rsqrtf(vr.x + BN_EPS), bt.x), 0.f);
        v.y = fmaxf(fmaf(v.y - mn.y, gm.y * rsqrtf(vr.y + BN_EPS), bt.y), 0.f);
        v.z = fmaxf(fmaf(v.z - mn.z, gm.z * rsqrtf(vr.z + BN_EPS), bt.z), 0.f);
        v.w = fmaxf(fmaf(v.w - mn.w, gm.w * rsqrtf(vr.w + BN_EPS), bt.w), 0.f);
    } else {
        v = reinterpret_cast<const float4*>(feats_b + (size_t)row * CB)[t - CA / 4];
    }
    __half2 h0 = __floats2half2_rn(v.x, v.y);
    __half2 h1 = __floats2half2_rn(v.z, v.w);
    __half* xs = g_xs + (size_t)row * CX + 4 * t;
    *reinterpret_cast<__half2*>(xs)     = h0;
    *reinterpret_cast<__half2*>(xs + 2) = h1;
}

// zero both fp32 accumulators in one kernel
__global__ void zero2_kernel(float* __restrict__ p0, float* __restrict__ p1, int n4) {
    int i = blockIdx.x * blockDim.x + threadIdx.x;
    if (i < n4) {
        reinterpret_cast<float4*>(p0)[i] = make_float4(0.f, 0.f, 0.f, 0.f);
        reinterpret_cast<float4*>(p1)[i] = make_float4(0.f, 0.f, 0.f, 0.f);
    }
}

// ===========================================================================
// Sparse conv (single fp16 pass): A fp16 x W fp16 -> fp32 acc -> red.v4
// EXACT R11 configuration (best known: 3581 us):
// CTA tile: 128 pairs x 256 out-ch. 512 threads, 16 warps (4M x 4N),
// warp tile 32x64 -> acc 64 regs/thread. K chunks of 32, 4-stage cp.async
// pipeline (wait_group 2). Epilogue staging overlays pipeline buffers
// (one syncthreads), SMEM 122880 B.
// ===========================================================================
#define OFF_B     10240
#define BUF_SZ    30720
#define NSTAGES   4
#define SMEM_TOTAL (NSTAGES * BUF_SZ)

template <int CIN, bool DST_GX>
__global__ void __launch_bounds__(512, 1)
spconv_mma_kernel(const __half* __restrict__ xs,
                  const __half* __restrict__ Wh,
                  const int* __restrict__ in_map,
                  const int* __restrict__ out_map,
                  float* __restrict__ out_param,
                  int M) {
    extern __shared__ char smc[];
    const uint32_t sb = smem_to_u32(smc);
    float* outb = DST_GX ? (float*)g_x : out_param;

    const int tid  = threadIdx.x;
    const int lane = tid & 31;
    const int w    = tid >> 5;       // 0..15
    const int wm   = w & 3;          // 4 M-groups of 32 rows
    const int wn   = w >> 2;         // 4 N-groups of 64 cols

    const int z  = blockIdx.z;
    const int m0 = blockIdx.x * 128;
    const size_t zM = (size_t)z * M;

    // ---- A gather: thread -> (row = tid>>2, 16B quarter = tid&3)
    const int ar = tid >> 2;         // 0..127
    const int as = tid & 3;
    const char* rowp = (const char*)xs;
    uint32_t zf = 0;
    if (m0 + ar < M) {
        rowp = (const char*)(xs + (size_t)in_map[zM + m0 + ar] * CIN);
        zf = 16;
    }
    const uint32_t dstA = sb + (uint32_t)(ar * 80 + as * 16);

    // ---- B: thread -> (n-row = tid>>1, 32B half = tid&1)
    const int br = tid >> 1;         // 0..255
    const int bs = tid & 1;
    const __half* hb = Wh + ((size_t)z * CO + br) * CIN + bs * 16;
    const uint32_t dstB = sb + OFF_B + (uint32_t)(br * 80 + bs * 32);

    // ---- ldmatrix lane addressing (bytes within a stage)
    const uint32_t aoff = (uint32_t)(((wm * 32 + (lane & 15)) * 40 + ((lane >> 4) * 8)) * 2);
    const uint32_t boff = (uint32_t)(((wn * 64 + (lane & 7) + ((lane >> 4) * 8)) * 40
                                      + (((lane >> 3) & 1) * 8)) * 2);

    float acc[2][8][4];
    #pragma unroll
    for (int i = 0; i < 2; ++i)
        #pragma unroll
        for (int j = 0; j < 8; ++j)
            #pragma unroll
            for (int q = 0; q < 4; ++q) acc[i][j][q] = 0.f;

    constexpr int NC = CIN / 32;

    auto load_chunk = [&](int c) {
        const uint32_t bo = (uint32_t)((c & (NSTAGES - 1)) * BUF_SZ);
        CP_ASYNC_16Z(dstA + bo, rowp + c * 64 + as * 16, zf);
        const __half* hk = hb + c * 32;
        CP_ASYNC_16(dstB + bo,      hk);
        CP_ASYNC_16(dstB + bo + 16, hk + 8);
    };

    load_chunk(0); CP_ASYNC_COMMIT();
    load_chunk(1); CP_ASYNC_COMMIT();
    load_chunk(2); CP_ASYNC_COMMIT();

    for (int c = 0; c < NC; ++c) {
        CP_ASYNC_WAIT2();
        __syncthreads();
        if (c + 3 < NC) load_chunk(c + 3);
        CP_ASYNC_COMMIT();

        const uint32_t bo = (uint32_t)((c & (NSTAGES - 1)) * BUF_SZ);
        #pragma unroll
        for (int ks = 0; ks < 2; ++ks) {
            const uint32_t ka = (uint32_t)(ks * 32);
            uint32_t ah[2][4];
            #pragma unroll
            for (int i = 0; i < 2; ++i) {
                uint32_t pa = sb + bo + aoff + ka + (uint32_t)(i * 1280);
                LDSM_X4(ah[i][0], ah[i][1], ah[i][2], ah[i][3], pa);
            }
            #pragma unroll
            for (int g = 0; g < 4; ++g) {
                uint32_t bh[4];
                uint32_t pb = sb + bo + OFF_B + boff + ka + (uint32_t)(g * 1280);
                LDSM_X4(bh[0], bh[1], bh[2], bh[3], pb);
                #pragma unroll
                for (int i = 0; i < 2; ++i) {
                    MMA_F16(acc[i][2 * g],     ah[i], bh);
                    MMA_F16(acc[i][2 * g + 1], ah[i], bh + 2);
                }
            }
        }
    }

    // ---- epilogue: per-warp SMEM transpose, coalesced red.v4
    __syncthreads();   // staging overlays the pipeline buffers
    float* ws = reinterpret_cast<float*>(smc) + w * (16 * 68);
    const int ncol = wn * 64 + (lane & 15) * 4;
    #pragma unroll
    for (int i = 0; i < 2; ++i) {
        #pragma unroll
        for (int j = 0; j < 8; ++j) {
            int colo = j * 8 + 2 * (lane & 3);
            *reinterpret_cast<float2*>(ws + (lane >> 2) * 68 + colo) =
                make_float2(acc[i][j][0], acc[i][j][1]);
            *reinterpret_cast<float2*>(ws + ((lane >> 2) + 8) * 68 + colo) =
                make_float2(acc[i][j][2], acc[i][j][3]);
        }
        __syncwarp();
        #pragma unroll
        for (int r = 0; r < 8; ++r) {
            int row = r * 2 + (lane >> 4);
            int mrow = m0 + wm * 32 + i * 16 + row;
            if (mrow < M) {
                int o = out_map[zM + mrow];
                float4 v = *reinterpret_cast<float4*>(ws + row * 68 + (lane & 15) * 4);
                red_add_v4(outb + (size_t)o * CO + ncol, v.x, v.y, v.z, v.w);
            }
        }
        __syncwarp();
    }
}

// ===========================================================================
// BN (eval) + ReLU on output
// ===========================================================================
__global__ void bn_relu_kernel(float* __restrict__ buf,
                               const float* __restrict__ gamma,
                               const float* __restrict__ beta,
                               const float* __restrict__ mean,
                               const float* __restrict__ var) {
    int c = threadIdx.x;
    float s  = gamma[c] * rsqrtf(var[c] + BN_EPS);
    float sh = beta[c] - mean[c] * s;
    for (int row = blockIdx.x; row < NB; row += gridDim.x) {
        size_t idx = (size_t)row * CO + c;
        buf[idx] = fmaxf(fmaf(buf[idx], s, sh), 0.f);
    }
}

// ===========================================================================
extern "C" void kernel_launch(void* const* d_in, const int* in_sizes, int n_in,
                              void* d_out, int out_size) {
    const float* feats_a    = (const float*)d_in[0];
    const float* feats_b    = (const float*)d_in[1];
    const float* W_t        = (const float*)d_in[2];
    const float* bn_t_gamma = (const float*)d_in[3];
    const float* bn_t_beta  = (const float*)d_in[4];
    const float* bn_t_mean  = (const float*)d_in[5];
    const float* bn_t_var   = (const float*)d_in[6];
    const float* W_c        = (const float*)d_in[7];
    const float* bn_c_gamma = (const float*)d_in[8];
    const float* bn_c_beta  = (const float*)d_in[9];
    const float* bn_c_mean  = (const float*)d_in[10];
    const float* bn_c_var   = (const float*)d_in[11];
    const int*   in_map_t   = (const int*)d_in[12];
    const int*   out_map_t  = (const int*)d_in[13];
    const int*   in_map_c   = (const int*)d_in[14];
    const int*   out_map_c  = (const int*)d_in[15];
    float* out = (float*)d_out;

    cudaFuncSetAttribute(spconv_mma_kernel<CA, true>,
                         cudaFuncAttributeMaxDynamicSharedMemorySize, SMEM_TOTAL);
    cudaFuncSetAttribute(spconv_mma_kernel<CX, false>,
                         cudaFuncAttributeMaxDynamicSharedMemorySize, SMEM_TOTAL);

    void *wt, *wc, *gx, *gas, *gxs;
    cudaGetSymbolAddress(&wt, g_Wt);
    cudaGetSymbolAddress(&wc, g_Wc);
    cudaGetSymbolAddress(&gx, g_x);
    cudaGetSymbolAddress(&gas, g_as);
    cudaGetSymbolAddress(&gxs, g_xs);

    // 0) weight transpose + fp16 ; feats_a fp16 ; zero accumulators
    prep_w_kernel<CA><<<dim3(CO / 32, CA / 32, KT), dim3(32, 8)>>>(W_t, (__half*)wt);
    prep_w_kernel<CX><<<dim3(CO / 32, CX / 32, KC), dim3(32, 8)>>>(W_c, (__half*)wc);
    prep_a_kernel<<<NA, 64>>>(feats_a);
    {
        int n4 = (int)((size_t)NB * CO / 4);
        zero2_kernel<<<(n4 + 255) / 256, 256>>>((float*)gx, out, n4);
    }

    // 1) transpose conv: g_as -> g_x (fp32 accum)
    {
        dim3 grid((MT + 127) / 128, 1, KT);
        spconv_mma_kernel<CA, true><<<grid, 512, SMEM_TOTAL>>>(
            (const __half*)gas, (const __half*)wt, in_map_t, out_map_t, nullptr, MT);
    }

    // 2) BN+ReLU + concat -> g_xs (fp16)
    bn_split_x_kernel<<<NB, 96>>>(feats_b, bn_t_gamma, bn_t_beta,
                                  bn_t_mean, bn_t_var);

    // 3) 3x3x3 conv: g_xs -> out
    {
        dim3 grid((MC + 127) / 128, 1, KC);
        spconv_mma_kernel<CX, false><<<grid, 512, SMEM_TOTAL>>>(
            (const __half*)gxs, (const __half*)wc, in_map_c, out_map_c, out, MC);
    }

    // 4) BN + ReLU on output
    bn_relu_kernel<<<4096, 256>>>(out, bn_c_gamma, bn_c_beta,
                                  bn_c_mean, bn_c_var);
}